// round 12
// baseline (speedup 1.0000x reference)
#include <cuda_runtime.h>
#include <cuda_fp16.h>
#include <cuda_bf16.h>

#define TT 12
#define CC 32
#define MAXN 131072
#define TBL_N 256            // entries per channel
#define TBL_STRIDE 257       // odd stride: bank = (c + slot) mod 32
#define TBL_LO (-6.0f)
#define TBL_SCALE (256.0f / 12.0f)   // entries per unit
#define TBL_H (12.0f / 256.0f)

// ---- bit-cast helpers ----
__device__ __forceinline__ unsigned h2_as_u32(__half2 h) {
    union { __half2 h; unsigned u; } cvt; cvt.h = h; return cvt.u;
}
__device__ __forceinline__ __half2 u32_as_h2(unsigned u) {
    union { unsigned u; __half2 h; } cvt; cvt.u = u; return cvt.h;
}

// ---- scratch (device globals; zero-init at load; kept zeroed by k_final) ----
__device__ float g_deg[MAXN];                    // Σ incoming w; re-zeroed by k_final
__device__ float g_dinv[MAXN];
__device__ __align__(128) uint2 g_yh[MAXN * 4];  // f16 y rows: 32B/node (24B used), sector-aligned
__device__ float g_agg[MAXN * TT];               // Σ w*y[s] (f32); re-zeroed by k_final
__device__ __align__(16) unsigned g_tbl[CC * TBL_STRIDE];  // half2 {g_i, delta_i}, XOR-swizzled slots
__device__ float g_probs[TT];                    // softmax(att)
__device__ float g_hw[CC];
__device__ float g_hb;

// vectorized global reduction: 4 floats per op
__device__ __forceinline__ void red4(float* p, float a, float b, float c, float d) {
    asm volatile("red.global.add.v4.f32 [%0], {%1, %2, %3, %4};"
                 :: "l"(p), "f"(a), "f"(b), "f"(c), "f"(d) : "memory");
}

// ---- K1: deg accumulation (blocks [0, degBlocks)) + consts/table build (block degBlocks) ----
__global__ void k_deg_consts(const int* __restrict__ ei, const float* __restrict__ ew, int e,
                             int degBlocks,
                             const float* __restrict__ w_z, const float* __restrict__ b_z,
                             const float* __restrict__ w_h, const float* __restrict__ b_h,
                             const float* __restrict__ lw_z, const float* __restrict__ lb_z,
                             const float* __restrict__ lw_h, const float* __restrict__ lb_h,
                             const float* __restrict__ att,
                             const float* __restrict__ head_w, const float* __restrict__ head_b) {
    if (blockIdx.x < (unsigned)degBlocks) {
        int base = (blockIdx.x * blockDim.x + threadIdx.x) * 4;
        if (base + 3 < e) {
            int4   d = *reinterpret_cast<const int4*>(ei + e + base);
            float4 w = *reinterpret_cast<const float4*>(ew + base);
            atomicAdd(&g_deg[d.x], w.x);
            atomicAdd(&g_deg[d.y], w.y);
            atomicAdd(&g_deg[d.z], w.z);
            atomicAdd(&g_deg[d.w], w.w);
        } else {
            for (int i = base; i < e; i++) atomicAdd(&g_deg[ei[e + i]], ew[i]);
        }
        return;
    }
    // ---- consts block: fold coefs, then build per-channel LUT ----
    __shared__ float s_az[CC], s_bz[CC], s_ah[CC], s_bh[CC];
    int o = threadIdx.x;
    if (o < CC) {
        float az = 0.f, bz = 0.f, ah = 0.f, bh = 0.f;
        const float* rz = lw_z + o * 2 * CC;   // torch layout [C, 2C]; first C cols used
        const float* rh = lw_h + o * 2 * CC;
        #pragma unroll
        for (int c = 0; c < CC; c++) {
            az += w_z[c] * rz[c];
            bz += b_z[c] * rz[c];
            ah += w_h[c] * rh[c];
            bh += b_h[c] * rh[c];
        }
        s_az[o] = az; s_bz[o] = bz + lb_z[o];
        s_ah[o] = ah; s_bh[o] = bh + lb_h[o];
        g_hw[o] = head_w[o];
    }
    if (o == 0) {
        float m = -1e30f;
        for (int t = 0; t < TT; t++) m = fmaxf(m, att[t]);
        float ex[TT]; float sum = 0.f;
        for (int t = 0; t < TT; t++) { ex[t] = expf(att[t] - m); sum += ex[t]; }
        for (int t = 0; t < TT; t++) g_probs[t] = ex[t] / sum;
        g_hb = head_b[0];
    }
    __syncthreads();
    // table: g_c(u) = (1 - sigmoid(az*u+bz)) * tanh(ah*u+bh), exact fp32 math.
    // slot layout: g_tbl[c*257 + (i ^ xc)], xc = (4c)&31, value = half2{g_i, g_{i+1}-g_i}
    for (int idx = threadIdx.x; idx < CC * TBL_N; idx += blockDim.x) {
        int c = idx >> 8;           // idx / 256
        int i = idx & 255;
        float az = s_az[c], bz = s_bz[c], ah = s_ah[c], bh = s_bh[c];
        float u0 = TBL_LO + (float)i * TBL_H;
        float u1 = u0 + TBL_H;
        float g0 = (1.0f - 1.0f / (1.0f + expf(-(az * u0 + bz)))) * tanhf(ah * u0 + bh);
        float g1 = (1.0f - 1.0f / (1.0f + expf(-(az * u1 + bz)))) * tanhf(ah * u1 + bh);
        int xc = (4 * c) & 31;
        g_tbl[c * TBL_STRIDE + (i ^ xc)] = h2_as_u32(__floats2half2_rn(g0, g1 - g0));
    }
}

// ---- K2: dinv + f16 y row (32B padded) ; one thread per node ----
__global__ void k_dinv_y(const float* __restrict__ x, int n) {
    int i = blockIdx.x * blockDim.x + threadIdx.x;
    if (i >= n) return;
    float di = rsqrtf(1.0f + g_deg[i]);   // +1 = self-loop weight; always > 0
    g_dinv[i] = di;
    const float4* xr = reinterpret_cast<const float4*>(x + (size_t)i * TT);
    float4 v0 = __ldg(xr + 0), v1 = __ldg(xr + 1), v2 = __ldg(xr + 2);
    uint4 a, b;
    a.x = h2_as_u32(__floats2half2_rn(di * v0.x, di * v0.y));
    a.y = h2_as_u32(__floats2half2_rn(di * v0.z, di * v0.w));
    a.z = h2_as_u32(__floats2half2_rn(di * v1.x, di * v1.y));
    a.w = h2_as_u32(__floats2half2_rn(di * v1.z, di * v1.w));
    b.x = h2_as_u32(__floats2half2_rn(di * v2.x, di * v2.y));
    b.y = h2_as_u32(__floats2half2_rn(di * v2.z, di * v2.w));
    b.z = 0u; b.w = 0u;
    uint4* yr = reinterpret_cast<uint4*>(g_yh + (size_t)i * 4);
    yr[0] = a;
    yr[1] = b;
}

// ---- K3: cooperative 3-lane edge scatter  agg[d,:] += w * y16[s,:] ----
// Uniform across lanes: lane part p loads uint2 (4 halves) at offset p*8B of the
// 32B row (1 sector), converts, red4s 16B of the f32 agg row. 10 edges/warp.
__global__ void k_scatter3h(const int* __restrict__ ei, const float* __restrict__ ew, int e) {
    int lane = threadIdx.x & 31;
    if (lane >= 30) return;
    int warp = (blockIdx.x * blockDim.x + threadIdx.x) >> 5;
    int grp  = lane / 3;               // 0..9
    int part = lane - grp * 3;         // 0..2
    int i = warp * 10 + grp;           // edge id
    if (i >= e) return;
    int s = __ldg(ei + i);
    int d = __ldg(ei + e + i);
    float w = __ldg(ew + i);
    uint2 h4 = __ldg(g_yh + (size_t)s * 4 + part);
    float2 f0 = __half22float2(u32_as_h2(h4.x));
    float2 f1 = __half22float2(u32_as_h2(h4.y));
    red4(g_agg + (size_t)d * TT + part * 4, w * f0.x, w * f0.y, w * f1.x, w * f1.y);
}

// ---- K4: LUT-based GRU-collapse, 4 threads/node (8 channels each) ----
// a[t] = dinv*agg[t] + dinv^2*x[t]; contribution = p_t * lerp(g_c, a_t).
// Per eval: 1 LDS.32 (half2 {g, delta}) + 1 HFMA2 (lo += p*g, hi += pf*delta).
__global__ void k_final4(const float* __restrict__ x, float* __restrict__ out, int n) {
    __shared__ unsigned s_tbl[CC * TBL_STRIDE];
    // cooperative table load (32.9KB, uint4 chunks; CC*TBL_STRIDE = 8224 = 2056*4)
    {
        const uint4* src = reinterpret_cast<const uint4*>(g_tbl);
        uint4* dst = reinterpret_cast<uint4*>(s_tbl);
        for (int k = threadIdx.x; k < (CC * TBL_STRIDE) / 4; k += blockDim.x)
            dst[k] = __ldg(src + k);
    }
    __syncthreads();

    int tid = blockIdx.x * blockDim.x + threadIdx.x;
    int node = tid >> 2;
    int q = tid & 3;                   // channel-quarter 0..3
    if (node >= n) return;
    float di = g_dinv[node];
    float di2 = di * di;
    float4* ap = reinterpret_cast<float4*>(g_agg + (size_t)node * TT);
    const float4* xp = reinterpret_cast<const float4*>(x + (size_t)node * TT);
    float4 a0 = ap[0], a1 = ap[1], a2 = ap[2];
    float4 x0 = __ldg(xp + 0), x1 = __ldg(xp + 1), x2 = __ldg(xp + 2);
    // distributed re-zero of scratch for next graph replay
    if (q < 3) ap[q] = make_float4(0.f, 0.f, 0.f, 0.f);
    else g_deg[node] = 0.0f;

    float a[TT] = {
        fmaf(di, a0.x, di2 * x0.x), fmaf(di, a0.y, di2 * x0.y),
        fmaf(di, a0.z, di2 * x0.z), fmaf(di, a0.w, di2 * x0.w),
        fmaf(di, a1.x, di2 * x1.x), fmaf(di, a1.y, di2 * x1.y),
        fmaf(di, a1.z, di2 * x1.z), fmaf(di, a1.w, di2 * x1.w),
        fmaf(di, a2.x, di2 * x2.x), fmaf(di, a2.y, di2 * x2.y),
        fmaf(di, a2.z, di2 * x2.z), fmaf(di, a2.w, di2 * x2.w)};

    int   islot[TT];       // table index (pre-swizzle)
    unsigned pw2[TT];      // half2 {p_t, p_t*frac_t}
    #pragma unroll
    for (int t = 0; t < TT; t++) {
        float p = g_probs[t];
        float u = fminf(fmaxf(a[t], TBL_LO), 5.999f);
        float fi = (u - TBL_LO) * TBL_SCALE;      // in [0, 255.98]
        int i = (int)fi;                           // trunc == floor (fi >= 0)
        float fr = fi - (float)i;
        islot[t] = i;
        pw2[t] = h2_as_u32(__floats2half2_rn(p, p * fr));
    }

    float acc = 0.f;
    int c0 = q * (CC / 4);
    #pragma unroll
    for (int cc = 0; cc < CC / 4; cc++) {
        int c = c0 + cc;
        int cbase = c * TBL_STRIDE;
        int xc = (4 * c) & 31;
        float hw = g_hw[c];
        __half2 hc2 = __float2half2_rn(0.f);
        #pragma unroll
        for (int t = 0; t < TT; t++) {
            unsigned v = s_tbl[cbase + (islot[t] ^ xc)];   // {g, delta}
            hc2 = __hfma2(u32_as_h2(pw2[t]), u32_as_h2(v), hc2);
        }
        float2 hcf = __half22float2(hc2);
        float hc = hcf.x + hcf.y;                 // p*g + p*frac*delta summed over t
        acc = fmaf(fmaxf(hc, 0.f), hw, acc);
    }
    // reduce the 4 channel-quarters (lanes q=0..3 of the same node share a warp)
    acc += __shfl_xor_sync(0xFFFFFFFFu, acc, 1);
    acc += __shfl_xor_sync(0xFFFFFFFFu, acc, 2);
    if (q == 0) out[node] = acc + g_hb;
}

extern "C" void kernel_launch(void* const* d_in, const int* in_sizes, int n_in,
                              void* d_out, int out_size) {
    const float* x      = (const float*)d_in[0];
    const int*   ei     = (const int*)  d_in[1];
    const float* ew     = (const float*)d_in[2];
    const float* w_z    = (const float*)d_in[3];
    const float* b_z    = (const float*)d_in[4];
    // d_in[5], d_in[6]: w_r, b_r — reset gate multiplies H=0, unused
    const float* w_h    = (const float*)d_in[7];
    const float* b_h    = (const float*)d_in[8];
    const float* lw_z   = (const float*)d_in[9];
    const float* lb_z   = (const float*)d_in[10];
    // d_in[11], d_in[12]: lw_r, lb_r — unused
    const float* lw_h   = (const float*)d_in[13];
    const float* lb_h   = (const float*)d_in[14];
    const float* att    = (const float*)d_in[15];
    const float* head_w = (const float*)d_in[16];
    const float* head_b = (const float*)d_in[17];
    float* out = (float*)d_out;

    int n = in_sizes[0] / TT;       // x is [N, T]
    int e = in_sizes[2];            // edge_weight is [E]
    if (n > MAXN) n = MAXN;

    const int B = 256;
    int gn  = (n + B - 1) / B;
    int gn4 = (n * 4 + B - 1) / B;
    int degBlocks = ((e + 3) / 4 + B - 1) / B;
    int gsc = (e + 79) / 80;        // 10 edges per warp, 8 warps/block

    k_deg_consts<<<degBlocks + 1, B>>>(ei, ew, e, degBlocks,
                                       w_z, b_z, w_h, b_h, lw_z, lb_z, lw_h, lb_h,
                                       att, head_w, head_b);
    k_dinv_y<<<gn, B>>>(x, n);
    k_scatter3h<<<gsc, B>>>(ei, ew, e);
    k_final4<<<gn4, B>>>(x, out, n);
}

// round 14
// speedup vs baseline: 1.1290x; 1.1290x over previous
#include <cuda_runtime.h>
#include <cuda_fp16.h>
#include <cuda_bf16.h>

#define TT 12
#define CC 32
#define MAXN 131072

// ---- bit-cast helpers ----
__device__ __forceinline__ unsigned h2_as_u32(__half2 h) {
    union { __half2 h; unsigned u; } cvt; cvt.h = h; return cvt.u;
}
__device__ __forceinline__ __half2 u32_as_h2(unsigned u) {
    union { unsigned u; __half2 h; } cvt; cvt.u = u; return cvt.h;
}

// ---- scratch (device globals; zero-init at load; kept zeroed by k_final) ----
__device__ float g_deg[MAXN];                    // Σ incoming w; re-zeroed by k_final
__device__ float g_dinv[MAXN];
__device__ __align__(128) uint4 g_yh[MAXN * 2];  // f16 y rows: 16 halves (12 used) = 32B
__device__ __align__(128) uint4 g_aggh[MAXN * 2];// f16 agg rows: 16 halves (12 used) = 32B; re-zeroed
__device__ __half2 g_hz_a[CC], g_hz_b[CC];       // broadcast half2: az/2, bz/2
__device__ __half2 g_hh_a[CC], g_hh_b[CC];       // broadcast half2: ah, bh
__device__ __half2 g_p2[TT / 2];                 // probs (0.5*softmax) as t-pairs
__device__ float g_hw[CC];
__device__ float g_hb;

__device__ __forceinline__ unsigned tanh2_fast(unsigned x) {  // tanh.approx on a half2 pair
    unsigned y;
    asm("tanh.approx.f16x2 %0, %1;" : "=r"(y) : "r"(x));
    return y;
}

// f16x2 vector reduction: 8 halves (16B) per lane-op
__device__ __forceinline__ void red4h2(unsigned* p, unsigned a, unsigned b, unsigned c, unsigned d) {
    asm volatile("red.global.add.noftz.v4.f16x2 [%0], {%1, %2, %3, %4};"
                 :: "l"(p), "r"(a), "r"(b), "r"(c), "r"(d) : "memory");
}

// ---- K1: deg accumulation (blocks [0, degBlocks)) + consts fold (block degBlocks) ----
__global__ void k_deg_consts(const int* __restrict__ ei, const float* __restrict__ ew, int e,
                             int degBlocks,
                             const float* __restrict__ w_z, const float* __restrict__ b_z,
                             const float* __restrict__ w_h, const float* __restrict__ b_h,
                             const float* __restrict__ lw_z, const float* __restrict__ lb_z,
                             const float* __restrict__ lw_h, const float* __restrict__ lb_h,
                             const float* __restrict__ att,
                             const float* __restrict__ head_w, const float* __restrict__ head_b) {
    if (blockIdx.x < (unsigned)degBlocks) {
        int base = (blockIdx.x * blockDim.x + threadIdx.x) * 4;
        if (base + 3 < e) {
            int4   d = *reinterpret_cast<const int4*>(ei + e + base);
            float4 w = *reinterpret_cast<const float4*>(ew + base);
            atomicAdd(&g_deg[d.x], w.x);
            atomicAdd(&g_deg[d.y], w.y);
            atomicAdd(&g_deg[d.z], w.z);
            atomicAdd(&g_deg[d.w], w.w);
        } else {
            for (int i = base; i < e; i++) atomicAdd(&g_deg[ei[e + i]], ew[i]);
        }
        return;
    }
    // ---- consts block ----
    int o = threadIdx.x;
    if (o < CC) {
        float az = 0.f, bz = 0.f, ah = 0.f, bh = 0.f;
        const float* rz = lw_z + o * 2 * CC;   // torch layout [C, 2C]; first C cols used
        const float* rh = lw_h + o * 2 * CC;
        #pragma unroll
        for (int c = 0; c < CC; c++) {
            az += w_z[c] * rz[c];
            bz += b_z[c] * rz[c];
            ah += w_h[c] * rh[c];
            bh += b_h[c] * rh[c];
        }
        g_hz_a[o] = __float2half2_rn(0.5f * az);
        g_hz_b[o] = __float2half2_rn(0.5f * (bz + lb_z[o]));
        g_hh_a[o] = __float2half2_rn(ah);
        g_hh_b[o] = __float2half2_rn(bh + lb_h[o]);
        g_hw[o] = head_w[o];
    }
    if (o == 0) {
        float m = -1e30f;
        for (int t = 0; t < TT; t++) m = fmaxf(m, att[t]);
        float ex[TT]; float sum = 0.f;
        for (int t = 0; t < TT; t++) { ex[t] = expf(att[t] - m); sum += ex[t]; }
        float inv = 0.5f / sum;                 // fold the 0.5 of (1-z)
        for (int t = 0; t < TT / 2; t++)
            g_p2[t] = __floats2half2_rn(ex[2 * t] * inv, ex[2 * t + 1] * inv);
        g_hb = head_b[0];
    }
}

// ---- K2: dinv + f16 y row (32B, 12 of 16 halves used) ; one thread per node ----
__global__ void k_dinv_y(const float* __restrict__ x, int n) {
    int i = blockIdx.x * blockDim.x + threadIdx.x;
    if (i >= n) return;
    float di = rsqrtf(1.0f + g_deg[i]);   // +1 = self-loop weight; always > 0
    g_dinv[i] = di;
    const float4* xr = reinterpret_cast<const float4*>(x + (size_t)i * TT);
    float4 v0 = __ldg(xr + 0), v1 = __ldg(xr + 1), v2 = __ldg(xr + 2);
    uint4 a, b;
    a.x = h2_as_u32(__floats2half2_rn(di * v0.x, di * v0.y));
    a.y = h2_as_u32(__floats2half2_rn(di * v0.z, di * v0.w));
    a.z = h2_as_u32(__floats2half2_rn(di * v1.x, di * v1.y));
    a.w = h2_as_u32(__floats2half2_rn(di * v1.z, di * v1.w));
    b.x = h2_as_u32(__floats2half2_rn(di * v2.x, di * v2.y));
    b.y = h2_as_u32(__floats2half2_rn(di * v2.z, di * v2.w));
    b.z = 0u; b.w = 0u;                   // pad halves 12..15 (stay zero through REDs)
    g_yh[(size_t)i * 2 + 0] = a;
    g_yh[(size_t)i * 2 + 1] = b;
}

// ---- K3: 2-lane edge scatter  aggh[d,:] += w * yh[s,:]  (f16x2 vector REDs) ----
// Uniform: lane part p loads uint4 (8 halves, 16B) at half-row p, REDs 16B.
// Pad halves are zero in y, so their REDs add 0. 16 edges/warp, all lanes used.
__global__ void k_scatter2v(const int* __restrict__ ei, const float* __restrict__ ew, int e) {
    int tid = blockIdx.x * blockDim.x + threadIdx.x;
    int eid = tid >> 1;
    int part = tid & 1;
    if (eid >= e) return;
    int s = __ldg(ei + eid);
    int d = __ldg(ei + e + eid);
    float w = __ldg(ew + eid);
    uint4 v = __ldg(g_yh + (size_t)s * 2 + part);
    __half2 wh = __float2half2_rn(w);
    unsigned r0 = h2_as_u32(__hmul2(u32_as_h2(v.x), wh));
    unsigned r1 = h2_as_u32(__hmul2(u32_as_h2(v.y), wh));
    unsigned r2 = h2_as_u32(__hmul2(u32_as_h2(v.z), wh));
    unsigned r3 = h2_as_u32(__hmul2(u32_as_h2(v.w), wh));
    red4h2(reinterpret_cast<unsigned*>(g_aggh + (size_t)d * 2 + part), r0, r1, r2, r3);
}

// ---- K4: pointwise GRU-collapse, 4 threads/node, packed half2 inner loop ----
// a[t] = dinv*(agg[t]+y[t]);  (1-z) = 0.5*(1 - tanh(zarg/2)); 0.5 folded into probs.
__global__ void k_final4(float* __restrict__ out, int n) {
    int tid = blockIdx.x * blockDim.x + threadIdx.x;
    int node = tid >> 2;
    int q = tid & 3;                   // channel-quarter 0..3
    if (node >= n) return;
    uint4* ahp = g_aggh + (size_t)node * 2;
    const uint4* yhp = g_yh + (size_t)node * 2;
    uint4 A0 = ahp[0], A1 = ahp[1];
    uint4 Y0 = __ldg(yhp + 0), Y1 = __ldg(yhp + 1);
    // distributed re-zero of scratch for next graph replay
    if (q == 0) ahp[0] = make_uint4(0u, 0u, 0u, 0u);
    else if (q == 1) ahp[1] = make_uint4(0u, 0u, 0u, 0u);
    else if (q == 2) g_deg[node] = 0.0f;
    __half2 dih = __float2half2_rn(g_dinv[node]);
    __half2 a2h[TT / 2];
    a2h[0] = __hmul2(dih, __hadd2(u32_as_h2(A0.x), u32_as_h2(Y0.x)));
    a2h[1] = __hmul2(dih, __hadd2(u32_as_h2(A0.y), u32_as_h2(Y0.y)));
    a2h[2] = __hmul2(dih, __hadd2(u32_as_h2(A0.z), u32_as_h2(Y0.z)));
    a2h[3] = __hmul2(dih, __hadd2(u32_as_h2(A0.w), u32_as_h2(Y0.w)));
    a2h[4] = __hmul2(dih, __hadd2(u32_as_h2(A1.x), u32_as_h2(Y1.x)));
    a2h[5] = __hmul2(dih, __hadd2(u32_as_h2(A1.y), u32_as_h2(Y1.y)));
    __half2 p2[TT / 2];
    #pragma unroll
    for (int t = 0; t < TT / 2; t++) p2[t] = g_p2[t];
    float acc = 0.f;
    int c0 = q * (CC / 4);
    #pragma unroll
    for (int cc = 0; cc < CC / 4; cc++) {
        int c = c0 + cc;
        __half2 za = g_hz_a[c], zb = g_hz_b[c];
        __half2 ha = g_hh_a[c], hb = g_hh_b[c];
        float hw = g_hw[c];
        __half2 hc2 = __float2half2_rn(0.f);
        #pragma unroll
        for (int t = 0; t < TT / 2; t++) {
            __half2 zarg = __hfma2(a2h[t], za, zb);
            __half2 harg = __hfma2(a2h[t], ha, hb);
            __half2 tz2 = u32_as_h2(tanh2_fast(h2_as_u32(zarg)));   // tanh(zarg/2)
            __half2 th2 = u32_as_h2(tanh2_fast(h2_as_u32(harg)));   // tanh(harg)
            __half2 term = __hsub2(th2, __hmul2(tz2, th2));          // (1-tz)*th
            hc2 = __hfma2(p2[t], term, hc2);
        }
        float hc = __low2float(hc2) + __high2float(hc2);
        acc = fmaf(fmaxf(hc, 0.f), hw, acc);
    }
    // reduce the 4 channel-quarters (lanes q=0..3 of the same node share a warp)
    acc += __shfl_xor_sync(0xFFFFFFFFu, acc, 1);
    acc += __shfl_xor_sync(0xFFFFFFFFu, acc, 2);
    if (q == 0) out[node] = acc + g_hb;
}

extern "C" void kernel_launch(void* const* d_in, const int* in_sizes, int n_in,
                              void* d_out, int out_size) {
    const float* x      = (const float*)d_in[0];
    const int*   ei     = (const int*)  d_in[1];
    const float* ew     = (const float*)d_in[2];
    const float* w_z    = (const float*)d_in[3];
    const float* b_z    = (const float*)d_in[4];
    // d_in[5], d_in[6]: w_r, b_r — reset gate multiplies H=0, unused
    const float* w_h    = (const float*)d_in[7];
    const float* b_h    = (const float*)d_in[8];
    const float* lw_z   = (const float*)d_in[9];
    const float* lb_z   = (const float*)d_in[10];
    // d_in[11], d_in[12]: lw_r, lb_r — unused
    const float* lw_h   = (const float*)d_in[13];
    const float* lb_h   = (const float*)d_in[14];
    const float* att    = (const float*)d_in[15];
    const float* head_w = (const float*)d_in[16];
    const float* head_b = (const float*)d_in[17];
    float* out = (float*)d_out;

    int n = in_sizes[0] / TT;       // x is [N, T]
    int e = in_sizes[2];            // edge_weight is [E]
    if (n > MAXN) n = MAXN;

    const int B = 256;
    int gn  = (n + B - 1) / B;
    int gn4 = (n * 4 + B - 1) / B;
    int degBlocks = ((e + 3) / 4 + B - 1) / B;
    int gsc = (e * 2 + B - 1) / B;  // 2 lanes per edge

    k_deg_consts<<<degBlocks + 1, B>>>(ei, ew, e, degBlocks,
                                       w_z, b_z, w_h, b_h, lw_z, lb_z, lw_h, lb_h,
                                       att, head_w, head_b);
    k_dinv_y<<<gn, B>>>(x, n);
    k_scatter2v<<<gsc, B>>>(ei, ew, e);
    k_final4<<<gn4, B>>>(out, n);
}

// round 15
// speedup vs baseline: 1.2157x; 1.0768x over previous
#include <cuda_runtime.h>
#include <cuda_fp16.h>
#include <cuda_bf16.h>

#define TT 12
#define CC 32
#define MAXN 131072

// ---- bit-cast helpers ----
__device__ __forceinline__ unsigned h2_as_u32(__half2 h) {
    union { __half2 h; unsigned u; } cvt; cvt.h = h; return cvt.u;
}
__device__ __forceinline__ __half2 u32_as_h2(unsigned u) {
    union { unsigned u; __half2 h; } cvt; cvt.u = u; return cvt.h;
}

// ---- scratch (device globals; zero-init at load; kept zeroed by k_final) ----
__device__ float g_deg[MAXN];                    // Σ incoming w; re-zeroed by k_final
__device__ float g_dinv[MAXN];
__device__ __align__(128) uint4 g_yh[MAXN * 2];  // f16 y rows: 16 halves (12 used) = 32B
__device__ __align__(128) uint4 g_aggh[MAXN * 2];// f16 agg rows: 16 halves (12 used) = 32B; re-zeroed
__device__ __half2 g_hz_a[CC], g_hz_b[CC];       // broadcast half2: az/2, bz/2
__device__ __half2 g_hh_a[CC], g_hh_b[CC];       // broadcast half2: ah, bh
__device__ __half2 g_p2[TT / 2];                 // probs (0.5*softmax) as t-pairs
__device__ float g_hw[CC];
__device__ float g_hb;

__device__ __forceinline__ unsigned tanh2_fast(unsigned x) {  // tanh.approx on a half2 pair
    unsigned y;
    asm("tanh.approx.f16x2 %0, %1;" : "=r"(y) : "r"(x));
    return y;
}

// f16x2 vector reduction: 8 halves (16B) per lane-op
__device__ __forceinline__ void red4h2(unsigned* p, unsigned a, unsigned b, unsigned c, unsigned d) {
    asm volatile("red.global.add.noftz.v4.f16x2 [%0], {%1, %2, %3, %4};"
                 :: "l"(p), "r"(a), "r"(b), "r"(c), "r"(d) : "memory");
}

// ---- K1: deg accumulation (blocks [0, degBlocks)) + consts fold (block degBlocks) ----
__global__ void k_deg_consts(const int* __restrict__ ei, const float* __restrict__ ew, int e,
                             int degBlocks,
                             const float* __restrict__ w_z, const float* __restrict__ b_z,
                             const float* __restrict__ w_h, const float* __restrict__ b_h,
                             const float* __restrict__ lw_z, const float* __restrict__ lb_z,
                             const float* __restrict__ lw_h, const float* __restrict__ lb_h,
                             const float* __restrict__ att,
                             const float* __restrict__ head_w, const float* __restrict__ head_b) {
#if __CUDA_ARCH__ >= 900
    cudaTriggerProgrammaticLaunchCompletion();   // let the next kernel dispatch early
#endif
    if (blockIdx.x < (unsigned)degBlocks) {
        int base = (blockIdx.x * blockDim.x + threadIdx.x) * 4;
        if (base + 3 < e) {
            int4   d = *reinterpret_cast<const int4*>(ei + e + base);
            float4 w = *reinterpret_cast<const float4*>(ew + base);
            atomicAdd(&g_deg[d.x], w.x);
            atomicAdd(&g_deg[d.y], w.y);
            atomicAdd(&g_deg[d.z], w.z);
            atomicAdd(&g_deg[d.w], w.w);
        } else {
            for (int i = base; i < e; i++) atomicAdd(&g_deg[ei[e + i]], ew[i]);
        }
        return;
    }
    // ---- consts block ----
    int o = threadIdx.x;
    if (o < CC) {
        float az = 0.f, bz = 0.f, ah = 0.f, bh = 0.f;
        const float* rz = lw_z + o * 2 * CC;   // torch layout [C, 2C]; first C cols used
        const float* rh = lw_h + o * 2 * CC;
        #pragma unroll
        for (int c = 0; c < CC; c++) {
            az += w_z[c] * rz[c];
            bz += b_z[c] * rz[c];
            ah += w_h[c] * rh[c];
            bh += b_h[c] * rh[c];
        }
        g_hz_a[o] = __float2half2_rn(0.5f * az);
        g_hz_b[o] = __float2half2_rn(0.5f * (bz + lb_z[o]));
        g_hh_a[o] = __float2half2_rn(ah);
        g_hh_b[o] = __float2half2_rn(bh + lb_h[o]);
        g_hw[o] = head_w[o];
    }
    if (o == 0) {
        float m = -1e30f;
        for (int t = 0; t < TT; t++) m = fmaxf(m, att[t]);
        float ex[TT]; float sum = 0.f;
        for (int t = 0; t < TT; t++) { ex[t] = expf(att[t] - m); sum += ex[t]; }
        float inv = 0.5f / sum;                 // fold the 0.5 of (1-z)
        for (int t = 0; t < TT / 2; t++)
            g_p2[t] = __floats2half2_rn(ex[2 * t] * inv, ex[2 * t + 1] * inv);
        g_hb = head_b[0];
    }
}

// ---- K2: dinv + f16 y row (32B, 12 of 16 halves used) ; one thread per node ----
// PDL: preload x row (external input), then wait for deg.
__global__ void k_dinv_y(const float* __restrict__ x, int n) {
    int i = blockIdx.x * blockDim.x + threadIdx.x;
    float4 v0, v1, v2;
    if (i < n) {
        const float4* xr = reinterpret_cast<const float4*>(x + (size_t)i * TT);
        v0 = __ldg(xr + 0); v1 = __ldg(xr + 1); v2 = __ldg(xr + 2);
    }
#if __CUDA_ARCH__ >= 900
    cudaTriggerProgrammaticLaunchCompletion();
    cudaGridDependencySynchronize();            // deg ready
#endif
    if (i >= n) return;
    float di = rsqrtf(1.0f + g_deg[i]);   // +1 = self-loop weight; always > 0
    g_dinv[i] = di;
    uint4 a, b;
    a.x = h2_as_u32(__floats2half2_rn(di * v0.x, di * v0.y));
    a.y = h2_as_u32(__floats2half2_rn(di * v0.z, di * v0.w));
    a.z = h2_as_u32(__floats2half2_rn(di * v1.x, di * v1.y));
    a.w = h2_as_u32(__floats2half2_rn(di * v1.z, di * v1.w));
    b.x = h2_as_u32(__floats2half2_rn(di * v2.x, di * v2.y));
    b.y = h2_as_u32(__floats2half2_rn(di * v2.z, di * v2.w));
    b.z = 0u; b.w = 0u;                   // pad halves 12..15 (stay zero through REDs)
    g_yh[(size_t)i * 2 + 0] = a;
    g_yh[(size_t)i * 2 + 1] = b;
}

// ---- K3: 2-lane edge scatter  aggh[d,:] += w * yh[s,:]  (f16x2 vector REDs) ----
// PDL: preload edge indices/weights (external inputs) during dinv_y's tail.
__global__ void k_scatter2v(const int* __restrict__ ei, const float* __restrict__ ew, int e) {
    int tid = blockIdx.x * blockDim.x + threadIdx.x;
    int eid = tid >> 1;
    int part = tid & 1;
    int s = 0, d = 0; float w = 0.f;
    bool act = eid < e;
    if (act) {
        s = __ldg(ei + eid);
        d = __ldg(ei + e + eid);
        w = __ldg(ew + eid);
    }
#if __CUDA_ARCH__ >= 900
    cudaTriggerProgrammaticLaunchCompletion();
    cudaGridDependencySynchronize();            // y rows ready
#endif
    if (!act) return;
    uint4 v = __ldg(g_yh + (size_t)s * 2 + part);
    __half2 wh = __float2half2_rn(w);
    unsigned r0 = h2_as_u32(__hmul2(u32_as_h2(v.x), wh));
    unsigned r1 = h2_as_u32(__hmul2(u32_as_h2(v.y), wh));
    unsigned r2 = h2_as_u32(__hmul2(u32_as_h2(v.z), wh));
    unsigned r3 = h2_as_u32(__hmul2(u32_as_h2(v.w), wh));
    red4h2(reinterpret_cast<unsigned*>(g_aggh + (size_t)d * 2 + part), r0, r1, r2, r3);
}

// ---- K4: pointwise GRU-collapse, 4 threads/node, packed half2 inner loop ----
// a[t] = dinv*(agg[t]+y[t]);  (1-z) = 0.5*(1 - tanh(zarg/2)); 0.5 folded into probs.
__global__ void k_final4(float* __restrict__ out, int n) {
#if __CUDA_ARCH__ >= 900
    cudaGridDependencySynchronize();            // agg ready (everything internal)
#endif
    int tid = blockIdx.x * blockDim.x + threadIdx.x;
    int node = tid >> 2;
    int q = tid & 3;                   // channel-quarter 0..3
    if (node >= n) return;
    uint4* ahp = g_aggh + (size_t)node * 2;
    const uint4* yhp = g_yh + (size_t)node * 2;
    uint4 A0 = ahp[0], A1 = ahp[1];
    uint4 Y0 = __ldg(yhp + 0), Y1 = __ldg(yhp + 1);
    // distributed re-zero of scratch for next graph replay
    if (q == 0) ahp[0] = make_uint4(0u, 0u, 0u, 0u);
    else if (q == 1) ahp[1] = make_uint4(0u, 0u, 0u, 0u);
    else if (q == 2) g_deg[node] = 0.0f;
    __half2 dih = __float2half2_rn(g_dinv[node]);
    __half2 a2h[TT / 2];
    a2h[0] = __hmul2(dih, __hadd2(u32_as_h2(A0.x), u32_as_h2(Y0.x)));
    a2h[1] = __hmul2(dih, __hadd2(u32_as_h2(A0.y), u32_as_h2(Y0.y)));
    a2h[2] = __hmul2(dih, __hadd2(u32_as_h2(A0.z), u32_as_h2(Y0.z)));
    a2h[3] = __hmul2(dih, __hadd2(u32_as_h2(A0.w), u32_as_h2(Y0.w)));
    a2h[4] = __hmul2(dih, __hadd2(u32_as_h2(A1.x), u32_as_h2(Y1.x)));
    a2h[5] = __hmul2(dih, __hadd2(u32_as_h2(A1.y), u32_as_h2(Y1.y)));
    __half2 p2[TT / 2];
    #pragma unroll
    for (int t = 0; t < TT / 2; t++) p2[t] = g_p2[t];
    float acc = 0.f;
    int c0 = q * (CC / 4);
    #pragma unroll
    for (int cc = 0; cc < CC / 4; cc++) {
        int c = c0 + cc;
        __half2 za = g_hz_a[c], zb = g_hz_b[c];
        __half2 ha = g_hh_a[c], hb = g_hh_b[c];
        float hw = g_hw[c];
        __half2 hc2 = __float2half2_rn(0.f);
        #pragma unroll
        for (int t = 0; t < TT / 2; t++) {
            __half2 zarg = __hfma2(a2h[t], za, zb);
            __half2 harg = __hfma2(a2h[t], ha, hb);
            __half2 tz2 = u32_as_h2(tanh2_fast(h2_as_u32(zarg)));   // tanh(zarg/2)
            __half2 th2 = u32_as_h2(tanh2_fast(h2_as_u32(harg)));   // tanh(harg)
            __half2 term = __hsub2(th2, __hmul2(tz2, th2));          // (1-tz)*th
            hc2 = __hfma2(p2[t], term, hc2);
        }
        float hc = __low2float(hc2) + __high2float(hc2);
        acc = fmaf(fmaxf(hc, 0.f), hw, acc);
    }
    // reduce the 4 channel-quarters (lanes q=0..3 of the same node share a warp)
    acc += __shfl_xor_sync(0xFFFFFFFFu, acc, 1);
    acc += __shfl_xor_sync(0xFFFFFFFFu, acc, 2);
    if (q == 0) out[node] = acc + g_hb;
}

extern "C" void kernel_launch(void* const* d_in, const int* in_sizes, int n_in,
                              void* d_out, int out_size) {
    const float* x      = (const float*)d_in[0];
    const int*   ei     = (const int*)  d_in[1];
    const float* ew     = (const float*)d_in[2];
    const float* w_z    = (const float*)d_in[3];
    const float* b_z    = (const float*)d_in[4];
    // d_in[5], d_in[6]: w_r, b_r — reset gate multiplies H=0, unused
    const float* w_h    = (const float*)d_in[7];
    const float* b_h    = (const float*)d_in[8];
    const float* lw_z   = (const float*)d_in[9];
    const float* lb_z   = (const float*)d_in[10];
    // d_in[11], d_in[12]: lw_r, lb_r — unused
    const float* lw_h   = (const float*)d_in[13];
    const float* lb_h   = (const float*)d_in[14];
    const float* att    = (const float*)d_in[15];
    const float* head_w = (const float*)d_in[16];
    const float* head_b = (const float*)d_in[17];
    float* out = (float*)d_out;

    int n = in_sizes[0] / TT;       // x is [N, T]
    int e = in_sizes[2];            // edge_weight is [E]
    if (n > MAXN) n = MAXN;

    const int B = 256;
    int gn  = (n + B - 1) / B;
    int gn4 = (n * 4 + B - 1) / B;
    int degBlocks = ((e + 3) / 4 + B - 1) / B;
    int gsc = (e * 2 + B - 1) / B;  // 2 lanes per edge

    // first kernel: normal launch
    k_deg_consts<<<degBlocks + 1, B>>>(ei, ew, e, degBlocks,
                                       w_z, b_z, w_h, b_h, lw_z, lb_z, lw_h, lb_h,
                                       att, head_w, head_b);

    // downstream kernels: programmatic dependent launch (overlap launch+prologue)
    cudaLaunchAttribute pdl[1];
    pdl[0].id = cudaLaunchAttributeProgrammaticStreamSerialization;
    pdl[0].val.programmaticStreamSerializationAllowed = 1;

    {
        cudaLaunchConfig_t cfg = {};
        cfg.gridDim = dim3(gn); cfg.blockDim = dim3(B);
        cfg.attrs = pdl; cfg.numAttrs = 1;
        cudaLaunchKernelEx(&cfg, k_dinv_y, x, n);
    }
    {
        cudaLaunchConfig_t cfg = {};
        cfg.gridDim = dim3(gsc); cfg.blockDim = dim3(B);
        cfg.attrs = pdl; cfg.numAttrs = 1;
        cudaLaunchKernelEx(&cfg, k_scatter2v, ei, ew, e);
    }
    {
        cudaLaunchConfig_t cfg = {};
        cfg.gridDim = dim3(gn4); cfg.blockDim = dim3(B);
        cfg.attrs = pdl; cfg.numAttrs = 1;
        cudaLaunchKernelEx(&cfg, k_final4, out, n);
    }
}